// round 16
// baseline (speedup 1.0000x reference)
#include <cuda_runtime.h>
#include <cstdint>

// ---------------------------------------------------------------------------
// GraphConv: out[node] = relu(sum(self+neighbors) @ W[deg(node)] + b[deg(node)])
// Counting-sort nodes by degree, then per-128-row-tile tf32 mma.sync GEMM with
// fused high-MLP neighbor gather (A tile in SMEM) and fused bias+relu epilogue.
// R14: 128-row tiles, warp grid 2Mx4N with 64x32 warp tiles (halves W traffic),
// CTA split into two independent 128-thread groups w/ named barriers (rows
// 0-63 / 64-127) -> 4 independent pipelines/SM, no CTA-wide barriers.
// NOTE: build targets plain sm_103 -> tcgen05/TMA unavailable; mma.sync it is.
// ---------------------------------------------------------------------------

#define NB      256
#define NNLOC   512
#define NNODES  (NB * NNLOC)      // 131072
#define DSLOTS  6
#define FIN     128
#define FOUT    128
#define NDEG    6
#define NTILE   128
#define MAXTILES 1030             // 131072/128 + 6

// ------------------------- device scratch (no allocs) ----------------------
__device__ int           g_nbr[NNODES * DSLOTS];
__device__ unsigned char g_deg[NNODES];
__device__ int           g_perm[NNODES];
__device__ int           g_hist[8];          // zero at load; k_prefix re-zeros
__device__ int           g_cnt[8];
__device__ int           g_grpbase[8];
__device__ int           g_tilebase[8];
__device__ int           g_totaltiles;
// W in B-fragment order: g_Wf[d][kk][n][la] = float2( Wt[n][kk*8+la], Wt[n][kk*8+la+4] )
// where Wt[n][k] = tf32(W[d][k][n]).  float2 index = ((d*16+kk)*128 + n)*4 + la
__device__ float2        g_Wf[NDEG * 16 * 128 * 4];

// ------------------------- helpers ------------------------------------------
__device__ __forceinline__ float to_tf32(float x) {
    uint32_t u = __float_as_uint(x), o;
    asm("cvt.rna.tf32.f32 %0, %1;" : "=r"(o) : "r"(u));
    return __uint_as_float(o);
}

__device__ __forceinline__ void bar_group(int id) {
    asm volatile("bar.sync %0, 128;" :: "r"(id) : "memory");
}

// ------------------------- kernel 1: deg/hist + W fragment prep -------------
__global__ void k_prep_deg(const float* __restrict__ W, const void* __restrict__ edges) {
    __shared__ int sh[6];
    __shared__ int s_is64;
    int tid = threadIdx.x;
    if (tid < 6) sh[tid] = 0;
    if (tid == 0) {
        // sniff edges dtype: int64 -> every odd 32-bit word is 0 or -1
        const int* e32 = (const int*)edges;
        int is64 = 1;
        #pragma unroll 8
        for (int i = 0; i < 128; i++) {
            int hi = e32[2 * i + 1];
            if (hi != 0 && hi != -1) { is64 = 0; break; }
        }
        s_is64 = is64;
    }
    __syncthreads();

    // --- degree + neighbor extraction for node g ---
    int g = blockIdx.x * 256 + tid;
    int deg = 0;
    int nb[6];
    if (s_is64) {
        const long long* e = (const long long*)edges + (size_t)g * 6;
        #pragma unroll
        for (int j = 0; j < 6; j++) { long long v = e[j]; nb[j] = (int)v; deg += (v >= 0); }
    } else {
        const int* e = (const int*)edges + (size_t)g * 6;
        #pragma unroll
        for (int j = 0; j < 6; j++) { int v = e[j]; nb[j] = v; deg += (v >= 0); }
    }
    #pragma unroll
    for (int j = 0; j < 6; j++) g_nbr[g * 6 + j] = nb[j];
    g_deg[g] = (unsigned char)deg;
    atomicAdd(&sh[deg], 1);
    __syncthreads();
    if (tid < 6) atomicAdd(&g_hist[tid], sh[tid]);

    // --- W fragment prep: 49152 float2, blocks 0..191 ---
    int fid = blockIdx.x * 256 + tid;
    if (fid < NDEG * 16 * 128 * 4) {
        int d  = fid >> 13;            // / 8192
        int r  = fid & 8191;
        int kk = r >> 9;               // / 512
        int r2 = r & 511;
        int n  = r2 >> 2;
        int la = r2 & 3;
        int k0 = kk * 8;
        float lo = to_tf32(W[(d * 128 + (k0 + la)) * 128 + n]);
        float hi = to_tf32(W[(d * 128 + (k0 + la + 4)) * 128 + n]);
        g_Wf[fid] = make_float2(lo, hi);
    }
}

// ------------------------- kernel 2: prefix (self-cleaning) -----------------
__global__ void k_prefix() {
    int b = 0, tb = 0;
    for (int d = 0; d < NDEG; d++) {
        g_grpbase[d]  = b;
        g_tilebase[d] = tb;
        b  += g_hist[d];
        tb += (g_hist[d] + NTILE - 1) / NTILE;
        g_cnt[d]  = 0;
        g_hist[d] = 0;                 // re-zero for next graph replay
    }
    g_grpbase[NDEG]  = b;
    g_tilebase[NDEG] = tb;
    g_totaltiles = tb;
}

// ------------------------- kernel 3: build permutation ----------------------
__global__ void k_perm() {
    __shared__ int s_loc[6], s_base[6];
    int tid = threadIdx.x;
    if (tid < 6) s_loc[tid] = 0;
    __syncthreads();
    int g = blockIdx.x * 256 + tid;
    int d = g_deg[g];
    int l = atomicAdd(&s_loc[d], 1);
    __syncthreads();
    if (tid < 6) s_base[tid] = atomicAdd(&g_cnt[tid], s_loc[tid]);
    __syncthreads();
    g_perm[g_grpbase[d] + s_base[d] + l] = g;
}

// ------------------------- kernel 4: fused gather + tf32 mma GEMM -----------
#define LDT 132  // padded A row stride (floats): conflict-free fragment loads

static constexpr unsigned OFF_NODE = 0;                  // 128 ints
static constexpr unsigned OFF_BIAS = 512;                // 2 groups x 128 floats
static constexpr unsigned OFF_NBR  = 1536;               // 128*6 ints = 3072
static constexpr unsigned OFF_A    = 4608;               // 128*132*4 = 67584
static constexpr unsigned SMEM_TOTAL = OFF_A + NTILE * LDT * 4;  // 72192 B

__global__ void __launch_bounds__(256, 2)
k_gemm(const float* __restrict__ atoms, const float* __restrict__ bias,
       float* __restrict__ out) {
    extern __shared__ __align__(16) unsigned char smem[];
    int tid = threadIdx.x, wid = tid >> 5, lane = tid & 31;
    int grp = tid >> 7;                 // 0: rows 0-63, 1: rows 64-127
    int gtid = tid & 127;
    int t = blockIdx.x;
    if (t >= g_totaltiles) return;   // uniform per CTA

    int d = 0;
    #pragma unroll
    for (int i = 0; i < NDEG - 1; i++)
        if (t >= g_tilebase[i + 1]) d = i + 1;
    int m0     = (t - g_tilebase[d]) * NTILE;
    int gstart = g_grpbase[d];
    int gcount = g_grpbase[d + 1] - g_grpbase[d];

    int*   sm_node = (int*)(smem + OFF_NODE);                  // [128]
    float* sm_bias = (float*)(smem + OFF_BIAS) + grp * 128;    // per-group copy
    int*   sm_nbr  = (int*)(smem + OFF_NBR);                   // [128][6]
    float* As      = (float*)(smem + OFF_A);                   // [128][LDT]

    // --- phase 1 (group-local): stage node ids + neighbor row ids + bias ---
    sm_bias[gtid] = bias[d * 128 + gtid];
    if (gtid < 64) {
        int row  = grp * 64 + gtid;
        int slot = m0 + row;
        int node = (slot < gcount) ? g_perm[gstart + slot] : -1;
        sm_node[row] = node;
        if (node >= 0) {
            int bb = node & ~(NNLOC - 1);
            const int2* nb2 = (const int2*)(g_nbr + node * 6);
            int2 e0 = nb2[0], e1 = nb2[1], e2 = nb2[2];
            sm_nbr[row * 6 + 0] = bb + e0.x;
            sm_nbr[row * 6 + 1] = bb + e0.y;
            sm_nbr[row * 6 + 2] = bb + e1.x;
            sm_nbr[row * 6 + 3] = bb + e1.y;
            sm_nbr[row * 6 + 4] = bb + e2.x;
            sm_nbr[row * 6 + 5] = bb + e2.y;
        }
    }
    bar_group(1 + grp);

    // --- phase 2 (group-local): gather, warp owns 16 rows, 4-row unroll ---
    {
        int rbase = grp * 64 + (wid & 3) * 16;
        #pragma unroll
        for (int i = 0; i < 16; i += 4) {
            float4 a4[4];
            int    nd[4];
            #pragma unroll
            for (int u = 0; u < 4; u++) {
                int r = rbase + i + u;
                nd[u] = sm_node[r];
                a4[u] = make_float4(0.f, 0.f, 0.f, 0.f);
                if (nd[u] >= 0)
                    a4[u] = ((const float4*)(atoms + ((size_t)nd[u] << 7)))[lane];
            }
            #pragma unroll
            for (int j = 0; j < 6; j++)
                if (j < d) {
                    #pragma unroll
                    for (int u = 0; u < 4; u++)
                        if (nd[u] >= 0) {
                            int gi = sm_nbr[(rbase + i + u) * 6 + j];
                            float4 v = ((const float4*)(atoms + ((size_t)gi << 7)))[lane];
                            a4[u].x += v.x; a4[u].y += v.y;
                            a4[u].z += v.z; a4[u].w += v.w;
                        }
                }
            #pragma unroll
            for (int u = 0; u < 4; u++) {
                a4[u].x = to_tf32(a4[u].x); a4[u].y = to_tf32(a4[u].y);
                a4[u].z = to_tf32(a4[u].z); a4[u].w = to_tf32(a4[u].w);
                *(float4*)&As[(rbase + i + u) * LDT + lane * 4] = a4[u];
            }
        }
    }
    bar_group(1 + grp);

    // --- phase 3: mma.sync tf32, group grid 1(M)x4(N), warp tile 64x32 ---
    int mb = grp * 64;                 // warp covers rows [mb, mb+64)
    int nbase = (wid & 3) * 32;
    int la = lane & 3, lg = lane >> 2;

    float acc[4][4][4];
    #pragma unroll
    for (int mt = 0; mt < 4; mt++)
        #pragma unroll
        for (int nt = 0; nt < 4; nt++)
            #pragma unroll
            for (int q = 0; q < 4; q++) acc[mt][nt][q] = 0.f;

    const uint32_t* Au = (const uint32_t*)As;
    // per-thread base into fragment-ordered W (float2 units)
    const float2* __restrict__ Wfd =
        g_Wf + ((size_t)d * 16 * 512) + (nbase + lg) * 4 + la;

    #pragma unroll
    for (int kk = 0; kk < 16; kk++) {
        int k0 = kk * 8;
        uint32_t a[4][4];
        #pragma unroll
        for (int mt = 0; mt < 4; mt++) {
            int r = mb + mt * 16 + lg;
            // PTX m16n8k8 tf32 A fragment: a0=(r,c) a1=(r+8,c) a2=(r,c+4) a3=(r+8,c+4)
            a[mt][0] = Au[r * LDT + k0 + la];
            a[mt][1] = Au[(r + 8) * LDT + k0 + la];
            a[mt][2] = Au[r * LDT + k0 + la + 4];
            a[mt][3] = Au[(r + 8) * LDT + k0 + la + 4];
        }
        const float2* wp = Wfd + kk * 512;
        #pragma unroll
        for (int nt = 0; nt < 4; nt++) {
            float2 bv = __ldg(wp + nt * 32);         // coalesced LDG.64, L1-resident
            uint32_t b0 = __float_as_uint(bv.x), b1 = __float_as_uint(bv.y);
            #pragma unroll
            for (int mt = 0; mt < 4; mt++)
                asm volatile(
                    "mma.sync.aligned.m16n8k8.row.col.f32.tf32.tf32.f32 "
                    "{%0,%1,%2,%3}, {%4,%5,%6,%7}, {%8,%9}, {%0,%1,%2,%3};"
                    : "+f"(acc[mt][nt][0]), "+f"(acc[mt][nt][1]),
                      "+f"(acc[mt][nt][2]), "+f"(acc[mt][nt][3])
                    : "r"(a[mt][0]), "r"(a[mt][1]), "r"(a[mt][2]), "r"(a[mt][3]),
                      "r"(b0), "r"(b1));
        }
    }

    // --- epilogue: direct gmem write, bias + relu (no barrier, no staging) ---
    // C fragment: c0,c1 at (row lg,   col la*2, la*2+1)
    //             c2,c3 at (row lg+8, col la*2, la*2+1)
    #pragma unroll
    for (int mt = 0; mt < 4; mt++) {
        int r  = mb + mt * 16 + lg;
        int n0 = sm_node[r];
        int n1 = sm_node[r + 8];
        #pragma unroll
        for (int nt = 0; nt < 4; nt++) {
            int c = nbase + nt * 8 + la * 2;
            float2 bv = *(float2*)&sm_bias[c];
            if (n0 >= 0) {
                float2 v = make_float2(fmaxf(acc[mt][nt][0] + bv.x, 0.f),
                                       fmaxf(acc[mt][nt][1] + bv.y, 0.f));
                *(float2*)(out + ((size_t)n0 << 7) + c) = v;
            }
            if (n1 >= 0) {
                float2 v = make_float2(fmaxf(acc[mt][nt][2] + bv.x, 0.f),
                                       fmaxf(acc[mt][nt][3] + bv.y, 0.f));
                *(float2*)(out + ((size_t)n1 << 7) + c) = v;
            }
        }
    }
}

// ------------------------- launch -------------------------------------------
extern "C" void kernel_launch(void* const* d_in, const int* in_sizes, int n_in,
                              void* d_out, int out_size) {
    const float* atoms = (const float*)d_in[0];
    const void*  edges = d_in[1];
    const float* W     = (const float*)d_in[2];
    const float* b     = (const float*)d_in[3];
    float* out = (float*)d_out;
    (void)in_sizes; (void)n_in; (void)out_size;

    cudaFuncSetAttribute(k_gemm, cudaFuncAttributeMaxDynamicSharedMemorySize, SMEM_TOTAL);

    k_prep_deg<<<NNODES / 256, 256>>>(W, edges);
    k_prefix<<<1, 1>>>();
    k_perm<<<NNODES / 256, 256>>>();
    k_gemm<<<MAXTILES, 256, SMEM_TOTAL>>>(atoms, b, out);
}